// round 3
// baseline (speedup 1.0000x reference)
#include <cuda_runtime.h>
#include <cuda_bf16.h>
#include <math_constants.h>
#include <float.h>

// VectorQuantizer: N=32768 rows, D=256, K=4096.
// R3: bf16 tensor-core (mma.sync) approximate distance filter with a certified
// error margin, then exact fp32 rescore of the candidate set (bit-identical to
// the reference chain verified exact in R1/R2). Superset guarantee: any k with
// exact dist <= exact min (incl. ties) satisfies
//   dist_hat(k) <= dist_hat_min + 2*eps  <= running_min + 2*eps
// so it is always collected; rescore then reproduces the reference argmin
// (lowest index on ties) exactly.

#define VQ_N 32768
#define VQ_D 256
#define VQ_K 4096

#define GM  128   // rows per CTA in gemm
#define GN   64   // codewords per tile
#define CAP  32   // candidate capacity per row
#define XW  132   // smem pitch in 32-bit words (264 bf16) -> conflict-free

__device__ __nv_bfloat16 g_xh[VQ_N * VQ_D];
__device__ __nv_bfloat16 g_ch[VQ_K * VQ_D];
__device__ float    g_A[VQ_N];
__device__ float    g_S1[VQ_N];
__device__ float    g_B[VQ_K];
__device__ unsigned g_cmaxbits;
__device__ int      g_candCnt[VQ_N];
__device__ int      g_cand[VQ_N * CAP];
__device__ int      g_ind[VQ_N];
__device__ double   g_losssum;

// ---------------------------------------------------------------- zero
__global__ void vq_zero_kernel() {
    int i = blockIdx.x * blockDim.x + threadIdx.x;
    if (i < VQ_N) g_candCnt[i] = 0;
    if (i == 0) { g_losssum = 0.0; g_cmaxbits = 0u; }
}

// ---------------------------------------------------------------- convert x -> bf16
__global__ void vq_convert_x(const float* __restrict__ x) {
    int i = blockIdx.x * blockDim.x + threadIdx.x;
    if (i >= VQ_N * VQ_D / 4) return;
    float4 v = ((const float4*)x)[i];
    __nv_bfloat162* dst = (__nv_bfloat162*)g_xh;
    __nv_bfloat162 p0, p1;
    p0.x = __float2bfloat16(v.x); p0.y = __float2bfloat16(v.y);
    p1.x = __float2bfloat16(v.z); p1.y = __float2bfloat16(v.w);
    dst[2 * i] = p0; dst[2 * i + 1] = p1;
}

// ---------------------------------------------------------------- convert c -> bf16 (+ max|c|)
__global__ void vq_convert_c(const float* __restrict__ cb) {
    __shared__ float smax[256];
    int i = blockIdx.x * blockDim.x + threadIdx.x;
    float m = 0.0f;
    if (i < VQ_K * VQ_D / 4) {
        float4 v = ((const float4*)cb)[i];
        __nv_bfloat162* dst = (__nv_bfloat162*)g_ch;
        __nv_bfloat162 p0, p1;
        p0.x = __float2bfloat16(v.x); p0.y = __float2bfloat16(v.y);
        p1.x = __float2bfloat16(v.z); p1.y = __float2bfloat16(v.w);
        dst[2 * i] = p0; dst[2 * i + 1] = p1;
        m = fmaxf(fmaxf(fabsf(v.x), fabsf(v.y)), fmaxf(fabsf(v.z), fabsf(v.w)));
    }
    smax[threadIdx.x] = m;
    __syncthreads();
    for (int s = 128; s > 0; s >>= 1) {
        if (threadIdx.x < s) smax[threadIdx.x] = fmaxf(smax[threadIdx.x], smax[threadIdx.x + s]);
        __syncthreads();
    }
    if (threadIdx.x == 0) atomicMax(&g_cmaxbits, __float_as_uint(smax[0]));
}

// ---------------------------------------------------------------- ||c_k||^2 exact
__global__ void vq_cbnorm_kernel(const float* __restrict__ cb) {
    int k = blockIdx.x * blockDim.x + threadIdx.x;
    if (k >= VQ_K) return;
    const float* c = cb + (size_t)k * VQ_D;
    float s = 0.0f;
    for (int i = 0; i < VQ_D; i++) {
        float v = c[i];
        s = __fadd_rn(s, __fmul_rn(v, v));   // strict sequential ascending
    }
    g_B[k] = s;
}

// ---------------------------------------------------------------- ||x_r||^2 exact + Sum|x|
__global__ void vq_rowsum_kernel(const float* __restrict__ x) {
    int r = blockIdx.x * blockDim.x + threadIdx.x;
    if (r >= VQ_N) return;
    const float* xr = x + (size_t)r * VQ_D;
    float s = 0.0f, s1 = 0.0f;
    for (int i = 0; i < VQ_D; i++) {
        float v = xr[i];
        s = __fadd_rn(s, __fmul_rn(v, v));   // strict sequential ascending
        s1 += fabsf(v);
    }
    g_A[r] = s;
    g_S1[r] = s1;
}

// ---------------------------------------------------------------- bf16 MMA gemm + candidate collect
__device__ __forceinline__ void mma16816(float c[4], unsigned a0, unsigned a1,
                                         unsigned a2, unsigned a3,
                                         unsigned b0, unsigned b1) {
    asm volatile(
        "mma.sync.aligned.m16n8k16.row.col.f32.bf16.bf16.f32 "
        "{%0,%1,%2,%3}, {%4,%5,%6,%7}, {%8,%9}, {%0,%1,%2,%3};\n"
        : "+f"(c[0]), "+f"(c[1]), "+f"(c[2]), "+f"(c[3])
        : "r"(a0), "r"(a1), "r"(a2), "r"(a3), "r"(b0), "r"(b1));
}

__global__ __launch_bounds__(256, 2) void vq_gemm_kernel() {
    extern __shared__ unsigned smem_dyn[];
    unsigned* xsw = smem_dyn;                  // GM x XW words (x tile, bf16 pairs)
    unsigned* csw = smem_dyn + GM * XW;        // GN x XW words (c tile)
    __shared__ unsigned s_rowmin[GM];

    const int tid  = threadIdx.x;
    const int w    = tid >> 5;
    const int lane = tid & 31;
    const int g    = lane >> 2;
    const int tg   = lane & 3;
    const int rowbase = (w >> 1) * 32;     // 4 row-groups of 32
    const int colbase = (w & 1) * 32;      // 2 col-groups of 32
    const int row0 = blockIdx.x * GM;

    // load x tile [GM x 256 bf16]
    for (int idx = tid; idx < GM * 32; idx += 256) {
        int r = idx >> 5, s = idx & 31;
        uint4 v = *((const uint4*)(g_xh + (size_t)(row0 + r) * VQ_D) + s);
        *((uint4*)(xsw + r * XW) + s) = v;
    }
    if (tid < GM) s_rowmin[tid] = 0x7f7fffffu;  // FLT_MAX bits

    // per-thread row metadata (4 rows: rowbase + mt*16 + pos*8 + g)
    int   lrow[4];
    float Arow[4], thr[4];
    float cmax = __uint_as_float(g_cmaxbits);
#pragma unroll
    for (int mi = 0; mi < 4; mi++) {
        int lr = rowbase + (mi >> 1) * 16 + (mi & 1) * 8 + g;
        lrow[mi] = lr;
        Arow[mi] = g_A[row0 + lr];
        // 2*eps: 2*(2*(2*2^-8+2^-16)+3.2e-5)*cmax*S1 + ulp slack, padded
        thr[mi]  = 0.033f * cmax * g_S1[row0 + lr] + 2.0e-4f;
    }

    for (int k0 = 0; k0 < VQ_K; k0 += GN) {
        // load c tile [GN x 256 bf16]
        for (int idx = tid; idx < GN * 32; idx += 256) {
            int r = idx >> 5, s = idx & 31;
            uint4 v = *((const uint4*)(g_ch + (size_t)(k0 + r) * VQ_D) + s);
            *((uint4*)(csw + r * XW) + s) = v;
        }
        __syncthreads();

        float acc[2][4][4];
#pragma unroll
        for (int mt = 0; mt < 2; mt++)
#pragma unroll
            for (int nt = 0; nt < 4; nt++)
#pragma unroll
                for (int q = 0; q < 4; q++) acc[mt][nt][q] = 0.0f;

#pragma unroll
        for (int d0 = 0; d0 < VQ_D; d0 += 16) {
            int dw = d0 >> 1;
            unsigned a[2][4];
#pragma unroll
            for (int mt = 0; mt < 2; mt++) {
                const unsigned* p  = xsw + (rowbase + mt * 16 + g) * XW + dw + tg;
                const unsigned* p8 = p + 8 * XW;
                a[mt][0] = p[0];  a[mt][2] = p[4];
                a[mt][1] = p8[0]; a[mt][3] = p8[4];
            }
#pragma unroll
            for (int nt = 0; nt < 4; nt++) {
                const unsigned* pb = csw + (colbase + nt * 8 + g) * XW + dw + tg;
                unsigned b0 = pb[0], b1 = pb[4];
                mma16816(acc[0][nt], a[0][0], a[0][1], a[0][2], a[0][3], b0, b1);
                mma16816(acc[1][nt], a[1][0], a[1][1], a[1][2], a[1][3], b0, b1);
            }
        }

        // epilogue phase 1: dist (in place), per-row local min, atomicMin
        const int kb = k0 + colbase;
        float lmin[4] = {FLT_MAX, FLT_MAX, FLT_MAX, FLT_MAX};
#pragma unroll
        for (int nt = 0; nt < 4; nt++) {
            float B0 = g_B[kb + nt * 8 + 2 * tg];
            float B1 = g_B[kb + nt * 8 + 2 * tg + 1];
#pragma unroll
            for (int mt = 0; mt < 2; mt++) {
                float d00 = (Arow[2 * mt] + B0)     - 2.0f * acc[mt][nt][0];
                float d01 = (Arow[2 * mt] + B1)     - 2.0f * acc[mt][nt][1];
                float d10 = (Arow[2 * mt + 1] + B0) - 2.0f * acc[mt][nt][2];
                float d11 = (Arow[2 * mt + 1] + B1) - 2.0f * acc[mt][nt][3];
                acc[mt][nt][0] = d00; acc[mt][nt][1] = d01;
                acc[mt][nt][2] = d10; acc[mt][nt][3] = d11;
                lmin[2 * mt]     = fminf(lmin[2 * mt],     fminf(d00, d01));
                lmin[2 * mt + 1] = fminf(lmin[2 * mt + 1], fminf(d10, d11));
            }
        }
#pragma unroll
        for (int mi = 0; mi < 4; mi++)
            atomicMin(&s_rowmin[lrow[mi]], __float_as_uint(lmin[mi]));
        __syncthreads();

        // epilogue phase 2: threshold check + append
        float rm[4];
#pragma unroll
        for (int mi = 0; mi < 4; mi++)
            rm[mi] = __uint_as_float(s_rowmin[lrow[mi]]) + thr[mi];
#pragma unroll
        for (int nt = 0; nt < 4; nt++) {
            int kA = kb + nt * 8 + 2 * tg;
#pragma unroll
            for (int mt = 0; mt < 2; mt++) {
#pragma unroll
                for (int q = 0; q < 4; q++) {
                    int mi = 2 * mt + (q >> 1);
                    if (acc[mt][nt][q] < rm[mi]) {
                        int grow = row0 + lrow[mi];
                        int pos = atomicAdd(&g_candCnt[grow], 1);
                        if (pos < CAP) g_cand[grow * CAP + pos] = kA + (q & 1);
                    }
                }
            }
        }
        // next iteration's cs load is ordered behind this tile's smem reads by
        // the phase-1 __syncthreads (mma reads complete before it).
        __syncthreads();
    }
}

// ---------------------------------------------------------------- exact rescore (warp per row)
__global__ void vq_rescore_kernel(const float* __restrict__ x,
                                  const float* __restrict__ cb) {
    int row  = blockIdx.x * 8 + (threadIdx.x >> 5);
    int lane = threadIdx.x & 31;
    if (row >= VQ_N) return;
    int cnt = g_candCnt[row];
    const float* xr = x + (size_t)row * VQ_D;
    float Ar = g_A[row];

    float best = FLT_MAX;
    int   besti = 0x7fffffff;
    if (cnt <= CAP) {
        if (lane < cnt) {
            int k = g_cand[row * CAP + lane];
            const float* ck = cb + (size_t)k * VQ_D;
            float acc = 0.0f;
            for (int i = 0; i < VQ_D; i++)
                acc = __fmaf_rn(__ldg(xr + i), __ldg(ck + i), acc);
            float t  = __fadd_rn(Ar, g_B[k]);
            float m2 = __fmul_rn(2.0f, acc);
            best  = __fsub_rn(t, m2);
            besti = k;
        }
    } else {
        // overflow fallback: full exact scan of this row (rare)
        for (int k = lane; k < VQ_K; k += 32) {
            const float* ck = cb + (size_t)k * VQ_D;
            float acc = 0.0f;
            for (int i = 0; i < VQ_D; i++)
                acc = __fmaf_rn(__ldg(xr + i), __ldg(ck + i), acc);
            float t  = __fadd_rn(Ar, g_B[k]);
            float m2 = __fmul_rn(2.0f, acc);
            float d  = __fsub_rn(t, m2);
            if (d < best || (d == best && k < besti)) { best = d; besti = k; }
        }
    }
    // warp lexicographic (value, index) reduction
#pragma unroll
    for (int off = 16; off > 0; off >>= 1) {
        float v = __shfl_down_sync(0xffffffffu, best, off);
        int   i = __shfl_down_sync(0xffffffffu, besti, off);
        if (v < best || (v == best && i < besti)) { best = v; besti = i; }
    }
    if (lane == 0) g_ind[row] = besti;
}

// ---------------------------------------------------------------- output + loss accum
__global__ void vq_output_kernel(const float* __restrict__ x,
                                 const float* __restrict__ cb,
                                 float* __restrict__ out)
{
    __shared__ double sd[256];
    int e4 = blockIdx.x * blockDim.x + threadIdx.x;
    double ls = 0.0;
    if (e4 < VQ_N * VQ_D / 4) {
        int base = e4 * 4;
        int row  = base >> 8;
        int col  = base & 255;
        int ind  = g_ind[row];
        float4 xv = *(const float4*)(x  + base);
        float4 qv = *(const float4*)(cb + (size_t)ind * VQ_D + col);
        float d0 = __fsub_rn(qv.x, xv.x);
        float d1 = __fsub_rn(qv.y, xv.y);
        float d2 = __fsub_rn(qv.z, xv.z);
        float d3 = __fsub_rn(qv.w, xv.w);
        float4 ov;
        ov.x = __fadd_rn(xv.x, d0);
        ov.y = __fadd_rn(xv.y, d1);
        ov.z = __fadd_rn(xv.z, d2);
        ov.w = __fadd_rn(xv.w, d3);
        *(float4*)(out + base) = ov;
        ls = (double)__fmul_rn(d0, d0) + (double)__fmul_rn(d1, d1)
           + (double)__fmul_rn(d2, d2) + (double)__fmul_rn(d3, d3);
    }
    sd[threadIdx.x] = ls;
    __syncthreads();
    for (int s = 128; s > 0; s >>= 1) {
        if (threadIdx.x < s) sd[threadIdx.x] += sd[threadIdx.x + s];
        __syncthreads();
    }
    if (threadIdx.x == 0) atomicAdd(&g_losssum, sd[0]);
}

// ---------------------------------------------------------------- finalize loss
__global__ void vq_finalize_kernel(float* __restrict__ out, int has_loss) {
    if (!has_loss) return;
    float m = (float)(g_losssum * (1.0 / (double)(VQ_N * VQ_D)));
    float commit = __fmul_rn(m, 0.25f);
    out[VQ_N * VQ_D] = __fadd_rn(commit, m);
}

// ---------------------------------------------------------------- launch
extern "C" void kernel_launch(void* const* d_in, const int* in_sizes, int n_in,
                              void* d_out, int out_size)
{
    const float* latents  = (const float*)d_in[0];
    const float* codebook = (const float*)d_in[1];
    if (n_in >= 2 && in_sizes[0] == VQ_K * VQ_D && in_sizes[1] == VQ_N * VQ_D) {
        latents  = (const float*)d_in[1];
        codebook = (const float*)d_in[0];
    }
    float* out = (float*)d_out;
    int has_loss = (out_size > VQ_N * VQ_D) ? 1 : 0;

    const int GEMM_SMEM = (GM * XW + GN * XW) * 4;   // 101376 bytes
    cudaFuncSetAttribute(vq_gemm_kernel,
                         cudaFuncAttributeMaxDynamicSharedMemorySize, GEMM_SMEM);

    vq_zero_kernel<<<VQ_N / 256, 256>>>();
    vq_convert_x<<<(VQ_N * VQ_D / 4) / 256, 256>>>(latents);
    vq_convert_c<<<(VQ_K * VQ_D / 4) / 256, 256>>>(codebook);
    vq_cbnorm_kernel<<<VQ_K / 256, 256>>>(codebook);
    vq_rowsum_kernel<<<VQ_N / 256, 256>>>(latents);
    vq_gemm_kernel<<<VQ_N / GM, 256, GEMM_SMEM>>>();
    vq_rescore_kernel<<<VQ_N / 8, 256>>>(latents, codebook);
    vq_output_kernel<<<(VQ_N * VQ_D / 4) / 256, 256>>>(latents, codebook, out);
    vq_finalize_kernel<<<1, 1>>>(out, has_loss);
}

// round 4
// speedup vs baseline: 9.6798x; 9.6798x over previous
#include <cuda_runtime.h>
#include <cuda_bf16.h>
#include <math_constants.h>
#include <float.h>

// VectorQuantizer: N=32768 rows, D=256, K=4096.
// bf16 tensor-core filter (certified margin) + exact fp32 rescore of the
// candidate set. Exact chain (verified rel_err=0.0 in R1-R3):
//   dist = fl( fl(A_r + B_k) - fl(2 * dot_seq_fma(x_r,c_k)) ), sequential
//   ascending-i fp32; argmin lowest-index on ties.
// R4: CAP 32->256 (prefix-min appends ~30-60/row overflowed CAP=32 and
// triggered mass full-scan fallback in R3); lane-strided rescore; coalesced
// fused prep kernels.

#define VQ_N 32768
#define VQ_D 256
#define VQ_K 4096

#define GM  128   // rows per CTA in gemm
#define GN   64   // codewords per tile
#define CAP 256   // candidate capacity per row
#define XW  132   // smem pitch in 32-bit words

__device__ __nv_bfloat16 g_xh[VQ_N * VQ_D];
__device__ __nv_bfloat16 g_ch[VQ_K * VQ_D];
__device__ float    g_A[VQ_N];
__device__ float    g_S1[VQ_N];
__device__ float    g_B[VQ_K];
__device__ unsigned g_cmaxbits;
__device__ int      g_candCnt[VQ_N];
__device__ int      g_cand[VQ_N * CAP];
__device__ int      g_ind[VQ_N];
__device__ double   g_losssum;

// ---------------------------------------------------------------- zero
__global__ void vq_zero_kernel() {
    int i = blockIdx.x * blockDim.x + threadIdx.x;
    if (i < VQ_N) g_candCnt[i] = 0;
    if (i == 0) { g_losssum = 0.0; g_cmaxbits = 0u; }
}

// ---------------------------------------------------------------- prep x: bf16 copy + exact norms
// 32 rows per block, 256 threads. Coalesced float4 loads; serial exact sums from smem.
__global__ __launch_bounds__(256) void vq_prep_x(const float* __restrict__ x) {
    __shared__ float sx[32][257];
    const int tid = threadIdx.x;
    const int row0 = blockIdx.x * 32;
#pragma unroll
    for (int it = 0; it < 8; it++) {
        int idx = tid + it * 256;          // 0..2047
        int r   = idx >> 6;                // row 0..31
        int c4  = idx & 63;                // float4 index 0..63
        float4 v = ((const float4*)(x + (size_t)(row0 + r) * VQ_D))[c4];
        sx[r][c4 * 4 + 0] = v.x; sx[r][c4 * 4 + 1] = v.y;
        sx[r][c4 * 4 + 2] = v.z; sx[r][c4 * 4 + 3] = v.w;
        __nv_bfloat162 p0, p1;
        p0.x = __float2bfloat16(v.x); p0.y = __float2bfloat16(v.y);
        p1.x = __float2bfloat16(v.z); p1.y = __float2bfloat16(v.w);
        __nv_bfloat162* dst = (__nv_bfloat162*)(g_xh + (size_t)(row0 + r) * VQ_D);
        dst[c4 * 2] = p0; dst[c4 * 2 + 1] = p1;
    }
    __syncthreads();
    if (tid < 32) {
        float s = 0.0f, s1 = 0.0f;
        for (int i = 0; i < VQ_D; i++) {
            float v = sx[tid][i];
            s  = __fadd_rn(s, __fmul_rn(v, v));   // strict sequential ascending
            s1 += fabsf(v);
        }
        g_A[row0 + tid]  = s;
        g_S1[row0 + tid] = s1;
    }
}

// ---------------------------------------------------------------- prep c: bf16 copy + exact ||c||^2 + max|c|
__global__ __launch_bounds__(256) void vq_prep_c(const float* __restrict__ cb) {
    __shared__ float sc[32][257];
    __shared__ float smax[256];
    const int tid = threadIdx.x;
    const int row0 = blockIdx.x * 32;
    float m = 0.0f;
#pragma unroll
    for (int it = 0; it < 8; it++) {
        int idx = tid + it * 256;
        int r   = idx >> 6;
        int c4  = idx & 63;
        float4 v = ((const float4*)(cb + (size_t)(row0 + r) * VQ_D))[c4];
        sc[r][c4 * 4 + 0] = v.x; sc[r][c4 * 4 + 1] = v.y;
        sc[r][c4 * 4 + 2] = v.z; sc[r][c4 * 4 + 3] = v.w;
        m = fmaxf(m, fmaxf(fmaxf(fabsf(v.x), fabsf(v.y)), fmaxf(fabsf(v.z), fabsf(v.w))));
        __nv_bfloat162 p0, p1;
        p0.x = __float2bfloat16(v.x); p0.y = __float2bfloat16(v.y);
        p1.x = __float2bfloat16(v.z); p1.y = __float2bfloat16(v.w);
        __nv_bfloat162* dst = (__nv_bfloat162*)(g_ch + (size_t)(row0 + r) * VQ_D);
        dst[c4 * 2] = p0; dst[c4 * 2 + 1] = p1;
    }
    smax[tid] = m;
    __syncthreads();
    if (tid < 32) {
        float s = 0.0f;
        for (int i = 0; i < VQ_D; i++) {
            float v = sc[tid][i];
            s = __fadd_rn(s, __fmul_rn(v, v));    // strict sequential ascending
        }
        g_B[row0 + tid] = s;
    }
    for (int s = 128; s > 0; s >>= 1) {
        if (tid < s) smax[tid] = fmaxf(smax[tid], smax[tid + s]);
        __syncthreads();
    }
    if (tid == 0) atomicMax(&g_cmaxbits, __float_as_uint(smax[0]));
}

// ---------------------------------------------------------------- bf16 MMA gemm + candidate collect
__device__ __forceinline__ void mma16816(float c[4], unsigned a0, unsigned a1,
                                         unsigned a2, unsigned a3,
                                         unsigned b0, unsigned b1) {
    asm volatile(
        "mma.sync.aligned.m16n8k16.row.col.f32.bf16.bf16.f32 "
        "{%0,%1,%2,%3}, {%4,%5,%6,%7}, {%8,%9}, {%0,%1,%2,%3};\n"
        : "+f"(c[0]), "+f"(c[1]), "+f"(c[2]), "+f"(c[3])
        : "r"(a0), "r"(a1), "r"(a2), "r"(a3), "r"(b0), "r"(b1));
}

__global__ __launch_bounds__(256, 2) void vq_gemm_kernel() {
    extern __shared__ unsigned smem_dyn[];
    unsigned* xsw = smem_dyn;                  // GM x XW words (x tile)
    unsigned* csw = smem_dyn + GM * XW;        // GN x XW words (c tile)
    __shared__ unsigned s_rowmin[GM];

    const int tid  = threadIdx.x;
    const int w    = tid >> 5;
    const int lane = tid & 31;
    const int g    = lane >> 2;
    const int tg   = lane & 3;
    const int rowbase = (w >> 1) * 32;
    const int colbase = (w & 1) * 32;
    const int row0 = blockIdx.x * GM;

    for (int idx = tid; idx < GM * 32; idx += 256) {
        int r = idx >> 5, s = idx & 31;
        uint4 v = *((const uint4*)(g_xh + (size_t)(row0 + r) * VQ_D) + s);
        *((uint4*)(xsw + r * XW) + s) = v;
    }
    if (tid < GM) s_rowmin[tid] = 0x7f7fffffu;

    int   lrow[4];
    float Arow[4], thr[4];
    float cmax = __uint_as_float(g_cmaxbits);
#pragma unroll
    for (int mi = 0; mi < 4; mi++) {
        int lr = rowbase + (mi >> 1) * 16 + (mi & 1) * 8 + g;
        lrow[mi] = lr;
        Arow[mi] = g_A[row0 + lr];
        // 2*eps certified: bf16 p=8 -> 2*(2*2^-8+2^-16)*2 ~ 0.0313; pad to 0.033
        thr[mi]  = 0.033f * cmax * g_S1[row0 + lr] + 4.0e-4f;
    }

    for (int k0 = 0; k0 < VQ_K; k0 += GN) {
        for (int idx = tid; idx < GN * 32; idx += 256) {
            int r = idx >> 5, s = idx & 31;
            uint4 v = *((const uint4*)(g_ch + (size_t)(k0 + r) * VQ_D) + s);
            *((uint4*)(csw + r * XW) + s) = v;
        }
        __syncthreads();

        float acc[2][4][4];
#pragma unroll
        for (int mt = 0; mt < 2; mt++)
#pragma unroll
            for (int nt = 0; nt < 4; nt++)
#pragma unroll
                for (int q = 0; q < 4; q++) acc[mt][nt][q] = 0.0f;

#pragma unroll
        for (int d0 = 0; d0 < VQ_D; d0 += 16) {
            int dw = d0 >> 1;
            unsigned a[2][4];
#pragma unroll
            for (int mt = 0; mt < 2; mt++) {
                const unsigned* p  = xsw + (rowbase + mt * 16 + g) * XW + dw + tg;
                const unsigned* p8 = p + 8 * XW;
                a[mt][0] = p[0];  a[mt][2] = p[4];
                a[mt][1] = p8[0]; a[mt][3] = p8[4];
            }
#pragma unroll
            for (int nt = 0; nt < 4; nt++) {
                const unsigned* pb = csw + (colbase + nt * 8 + g) * XW + dw + tg;
                unsigned b0 = pb[0], b1 = pb[4];
                mma16816(acc[0][nt], a[0][0], a[0][1], a[0][2], a[0][3], b0, b1);
                mma16816(acc[1][nt], a[1][0], a[1][1], a[1][2], a[1][3], b0, b1);
            }
        }

        const int kb = k0 + colbase;
        float lmin[4] = {FLT_MAX, FLT_MAX, FLT_MAX, FLT_MAX};
#pragma unroll
        for (int nt = 0; nt < 4; nt++) {
            float B0 = g_B[kb + nt * 8 + 2 * tg];
            float B1 = g_B[kb + nt * 8 + 2 * tg + 1];
#pragma unroll
            for (int mt = 0; mt < 2; mt++) {
                float d00 = (Arow[2 * mt] + B0)     - 2.0f * acc[mt][nt][0];
                float d01 = (Arow[2 * mt] + B1)     - 2.0f * acc[mt][nt][1];
                float d10 = (Arow[2 * mt + 1] + B0) - 2.0f * acc[mt][nt][2];
                float d11 = (Arow[2 * mt + 1] + B1) - 2.0f * acc[mt][nt][3];
                acc[mt][nt][0] = d00; acc[mt][nt][1] = d01;
                acc[mt][nt][2] = d10; acc[mt][nt][3] = d11;
                lmin[2 * mt]     = fminf(lmin[2 * mt],     fminf(d00, d01));
                lmin[2 * mt + 1] = fminf(lmin[2 * mt + 1], fminf(d10, d11));
            }
        }
#pragma unroll
        for (int mi = 0; mi < 4; mi++)
            atomicMin(&s_rowmin[lrow[mi]], __float_as_uint(lmin[mi]));
        __syncthreads();

        float rm[4];
#pragma unroll
        for (int mi = 0; mi < 4; mi++)
            rm[mi] = __uint_as_float(s_rowmin[lrow[mi]]) + thr[mi];
#pragma unroll
        for (int nt = 0; nt < 4; nt++) {
            int kA = kb + nt * 8 + 2 * tg;
#pragma unroll
            for (int mt = 0; mt < 2; mt++) {
#pragma unroll
                for (int q = 0; q < 4; q++) {
                    int mi = 2 * mt + (q >> 1);
                    if (acc[mt][nt][q] < rm[mi]) {
                        int grow = row0 + lrow[mi];
                        int pos = atomicAdd(&g_candCnt[grow], 1);
                        if (pos < CAP) g_cand[grow * CAP + pos] = kA + (q & 1);
                    }
                }
            }
        }
        __syncthreads();
    }
}

// ---------------------------------------------------------------- exact rescore (warp per row, lane-strided)
__device__ __forceinline__ float exact_dist(const float* __restrict__ xr,
                                            const float* __restrict__ ck,
                                            float Ar, float Bk) {
    float acc = 0.0f;
    const float4* x4 = (const float4*)xr;
    const float4* c4 = (const float4*)ck;
#pragma unroll 4
    for (int i = 0; i < VQ_D / 4; i++) {
        float4 a = __ldg(x4 + i);
        float4 b = __ldg(c4 + i);
        acc = __fmaf_rn(a.x, b.x, acc);
        acc = __fmaf_rn(a.y, b.y, acc);
        acc = __fmaf_rn(a.z, b.z, acc);
        acc = __fmaf_rn(a.w, b.w, acc);
    }
    float t  = __fadd_rn(Ar, Bk);
    float m2 = __fmul_rn(2.0f, acc);
    return __fsub_rn(t, m2);
}

__global__ void vq_rescore_kernel(const float* __restrict__ x,
                                  const float* __restrict__ cb) {
    int row  = blockIdx.x * 8 + (threadIdx.x >> 5);
    int lane = threadIdx.x & 31;
    if (row >= VQ_N) return;
    int cnt = g_candCnt[row];
    const float* xr = x + (size_t)row * VQ_D;
    float Ar = g_A[row];

    float best = FLT_MAX;
    int   besti = 0x7fffffff;
    if (cnt <= CAP) {
        for (int j = lane; j < cnt; j += 32) {
            int k = g_cand[row * CAP + j];
            float d = exact_dist(xr, cb + (size_t)k * VQ_D, Ar, g_B[k]);
            if (d < best || (d == best && k < besti)) { best = d; besti = k; }
        }
    } else {
        for (int k = lane; k < VQ_K; k += 32) {
            float d = exact_dist(xr, cb + (size_t)k * VQ_D, Ar, g_B[k]);
            if (d < best || (d == best && k < besti)) { best = d; besti = k; }
        }
    }
#pragma unroll
    for (int off = 16; off > 0; off >>= 1) {
        float v = __shfl_down_sync(0xffffffffu, best, off);
        int   i = __shfl_down_sync(0xffffffffu, besti, off);
        if (v < best || (v == best && i < besti)) { best = v; besti = i; }
    }
    if (lane == 0) g_ind[row] = besti;
}

// ---------------------------------------------------------------- output + loss accum
__global__ void vq_output_kernel(const float* __restrict__ x,
                                 const float* __restrict__ cb,
                                 float* __restrict__ out)
{
    __shared__ double sd[256];
    int e4 = blockIdx.x * blockDim.x + threadIdx.x;
    double ls = 0.0;
    if (e4 < VQ_N * VQ_D / 4) {
        int base = e4 * 4;
        int row  = base >> 8;
        int col  = base & 255;
        int ind  = g_ind[row];
        float4 xv = *(const float4*)(x  + base);
        float4 qv = *(const float4*)(cb + (size_t)ind * VQ_D + col);
        float d0 = __fsub_rn(qv.x, xv.x);
        float d1 = __fsub_rn(qv.y, xv.y);
        float d2 = __fsub_rn(qv.z, xv.z);
        float d3 = __fsub_rn(qv.w, xv.w);
        float4 ov;
        ov.x = __fadd_rn(xv.x, d0);
        ov.y = __fadd_rn(xv.y, d1);
        ov.z = __fadd_rn(xv.z, d2);
        ov.w = __fadd_rn(xv.w, d3);
        *(float4*)(out + base) = ov;
        ls = (double)__fmul_rn(d0, d0) + (double)__fmul_rn(d1, d1)
           + (double)__fmul_rn(d2, d2) + (double)__fmul_rn(d3, d3);
    }
    sd[threadIdx.x] = ls;
    __syncthreads();
    for (int s = 128; s > 0; s >>= 1) {
        if (threadIdx.x < s) sd[threadIdx.x] += sd[threadIdx.x + s];
        __syncthreads();
    }
    if (threadIdx.x == 0) atomicAdd(&g_losssum, sd[0]);
}

// ---------------------------------------------------------------- finalize loss
__global__ void vq_finalize_kernel(float* __restrict__ out, int has_loss) {
    if (!has_loss) return;
    float m = (float)(g_losssum * (1.0 / (double)(VQ_N * VQ_D)));
    float commit = __fmul_rn(m, 0.25f);
    out[VQ_N * VQ_D] = __fadd_rn(commit, m);
}

// ---------------------------------------------------------------- launch
extern "C" void kernel_launch(void* const* d_in, const int* in_sizes, int n_in,
                              void* d_out, int out_size)
{
    const float* latents  = (const float*)d_in[0];
    const float* codebook = (const float*)d_in[1];
    if (n_in >= 2 && in_sizes[0] == VQ_K * VQ_D && in_sizes[1] == VQ_N * VQ_D) {
        latents  = (const float*)d_in[1];
        codebook = (const float*)d_in[0];
    }
    float* out = (float*)d_out;
    int has_loss = (out_size > VQ_N * VQ_D) ? 1 : 0;

    const int GEMM_SMEM = (GM * XW + GN * XW) * 4;   // 101376 bytes
    cudaFuncSetAttribute(vq_gemm_kernel,
                         cudaFuncAttributeMaxDynamicSharedMemorySize, GEMM_SMEM);

    vq_zero_kernel<<<VQ_N / 256, 256>>>();
    vq_prep_c<<<VQ_K / 32, 256>>>(codebook);
    vq_prep_x<<<VQ_N / 32, 256>>>(latents);
    vq_gemm_kernel<<<VQ_N / GM, 256, GEMM_SMEM>>>();
    vq_rescore_kernel<<<VQ_N / 8, 256>>>(latents, codebook);
    vq_output_kernel<<<(VQ_N * VQ_D / 4) / 256, 256>>>(latents, codebook, out);
    vq_finalize_kernel<<<1, 1>>>(out, has_loss);
}